// round 13
// baseline (speedup 1.0000x reference)
#include <cuda_runtime.h>
#include <cuda_fp16.h>
#include <cstdint>

constexpr int kD = 512, kInner = 512, kVocab = 2048;
constexpr int kEncRows = 1024, kDecRows = 256, kMRows = 65536;

__device__ float g_eproj2[2][kEncRows * kInner];    // K-split halves of enc @ We (+b1 in half 0)
__device__ float g_dproj2[2][kDecRows * kInner];    // K-split halves of dec @ Wd
__device__ __half g_w2h[(size_t)kVocab * kInner];   // W2^T as fp16, [v][k]
__device__ __half g_hidden[(size_t)kMRows * kInner]; // tanh(...) as fp16, [m][k] (67MB)

// ---------------- helpers ----------------
__device__ __forceinline__ uint32_t smem_u32(const void* p) {
    uint32_t a;
    asm("{ .reg .u64 t; cvta.to.shared.u64 t, %1; cvt.u32.u64 %0, t; }" : "=r"(a) : "l"(p));
    return a;
}
#define CP_COMMIT() asm volatile("cp.async.commit_group;" ::: "memory")
#define CP_WAIT0()  asm volatile("cp.async.wait_group 0;" ::: "memory")
__device__ __forceinline__ void cpasync16(uint32_t dst, const void* src) {
    asm volatile("cp.async.cg.shared.global [%0], [%1], 16;" :: "r"(dst), "l"(src) : "memory");
}
#define LDSM_X4(r0, r1, r2, r3, a) \
    asm volatile("ldmatrix.sync.aligned.m8n8.x4.shared.b16 {%0,%1,%2,%3}, [%4];" \
                 : "=r"(r0), "=r"(r1), "=r"(r2), "=r"(r3) : "r"(a))
__device__ __forceinline__ void mma16816(float* c, const uint32_t* a, const uint32_t* b) {
    asm volatile("mma.sync.aligned.m16n8k16.row.col.f32.f16.f16.f32 "
                 "{%0,%1,%2,%3}, {%4,%5,%6,%7}, {%8,%9}, {%0,%1,%2,%3};"
                 : "+f"(c[0]), "+f"(c[1]), "+f"(c[2]), "+f"(c[3])
                 : "r"(a[0]), "r"(a[1]), "r"(a[2]), "r"(a[3]), "r"(b[0]), "r"(b[1]));
}
__device__ __forceinline__ void stcs_f2(float* p, float2 v) {
    asm volatile("st.global.cs.v2.f32 [%0], {%1,%2};" :: "l"(p), "f"(v.x), "f"(v.y) : "memory");
}
// proven tanh (same formulation that measured rel_err 2.854e-4)
__device__ __forceinline__ float fast_tanh(float x) {
    float e = __expf(2.0f * x);
    return 1.0f - __fdividef(2.0f, e + 1.0f);
}
__device__ __forceinline__ uint32_t pack_h2(float lo, float hi) {
    uint32_t r;
    asm("cvt.rn.f16x2.f32 %0, %1, %2;" : "=r"(r) : "f"(hi), "f"(lo));
    return r;
}

// ---------------- K1: prep = proj (K-split x2, 640 blocks) + w2h (1024 blocks) --
__global__ void prep_kernel(const float* __restrict__ enc, const float* __restrict__ dec,
                            const float* __restrict__ W1, const float* __restrict__ b1,
                            const float* __restrict__ W2)
{
    const int bid = blockIdx.x;
    const int tid = threadIdx.x;
    if (bid < 1024) {
        __shared__ float tile[32][33];
        const int tx = tid & 31, ty = tid >> 5;
        const int v0 = (bid & 63) * 32, k0 = (bid >> 6) * 32;
#pragma unroll
        for (int i = 0; i < 4; i++)
            tile[ty + i * 8][tx] = W2[(size_t)(k0 + ty + i * 8) * kVocab + v0 + tx];
        __syncthreads();
#pragma unroll
        for (int i = 0; i < 4; i++)
            g_w2h[(size_t)(v0 + ty + i * 8) * kInner + k0 + tx] = __float2half_rn(tile[tx][ty + i * 8]);
        return;
    }
    __shared__ float As[16][34];
    __shared__ float Ws[16][64];
    const int bid2 = bid - 1024;
    const int bm = bid2 >> 4;
    const int bn = (bid2 & 15) >> 1;
    const int half = bid2 & 1;
    const int row0 = bm * 32;
    const bool is_enc = row0 < kEncRows;
    const float* in = (is_enc ? (enc + row0 * kD) : (dec + (row0 - kEncRows) * kD)) + half * 256;
    const float* W  = (is_enc ? W1 : (W1 + kD * kInner)) + (size_t)half * 256 * kInner;
    const int tx = tid & 15, ty = tid >> 4;

    float acc[2][4];
#pragma unroll
    for (int i = 0; i < 2; i++)
#pragma unroll
        for (int j = 0; j < 4; j++) acc[i][j] = 0.f;

    for (int kt = 0; kt < 16; kt++) {
        float2 av = *(const float2*)(in + (tid >> 3) * kD + kt * 16 + (tid & 7) * 2);
        float4 wv = *(const float4*)(W + (kt * 16 + (tid >> 4)) * kInner + bn * 64 + (tid & 15) * 4);
        As[(tid & 7) * 2 + 0][tid >> 3] = av.x;
        As[(tid & 7) * 2 + 1][tid >> 3] = av.y;
        *(float4*)&Ws[tid >> 4][(tid & 15) * 4] = wv;
        __syncthreads();
#pragma unroll
        for (int k = 0; k < 16; k++) {
            float ar[2], br[4];
#pragma unroll
            for (int i = 0; i < 2; i++) ar[i] = As[k][ty * 2 + i];
#pragma unroll
            for (int j = 0; j < 4; j++) br[j] = Ws[k][tx * 4 + j];
#pragma unroll
            for (int i = 0; i < 2; i++)
#pragma unroll
                for (int j = 0; j < 4; j++) acc[i][j] += ar[i] * br[j];
        }
        __syncthreads();
    }
    float* outp = is_enc ? g_eproj2[half] : g_dproj2[half];
    const int obase = is_enc ? row0 : (row0 - kEncRows);
#pragma unroll
    for (int i = 0; i < 2; i++)
#pragma unroll
        for (int j = 0; j < 4; j++) {
            const int n = bn * 64 + tx * 4 + j;
            float v = acc[i][j];
            if (is_enc && half == 0) v += b1[n];
            outp[(obase + ty * 2 + i) * kInner + n] = v;
        }
}

// ---------------- K2: hidden = tanh(sum of 4 partials) -> fp16 [m][k] ---------
__global__ void hidden_kernel()
{
    const int t = blockIdx.x * 256 + threadIdx.x;  // 4.19M threads, 8 halves each
    const int row = t >> 6;
    const int c8 = (t & 63) * 8;
    const int er = row >> 6;
    const int dr = ((row >> 14) << 6) | (row & 63);
    const float* e0 = g_eproj2[0] + (size_t)er * kInner + c8;
    const float* e1 = g_eproj2[1] + (size_t)er * kInner + c8;
    const float* d0 = g_dproj2[0] + (size_t)dr * kInner + c8;
    const float* d1 = g_dproj2[1] + (size_t)dr * kInner + c8;
    uint4 o;
    {
        float4 a = *(const float4*)e0, b = *(const float4*)e1;
        float4 c = *(const float4*)d0, d = *(const float4*)d1;
        o.x = pack_h2(fast_tanh(a.x + b.x + c.x + d.x), fast_tanh(a.y + b.y + c.y + d.y));
        o.y = pack_h2(fast_tanh(a.z + b.z + c.z + d.z), fast_tanh(a.w + b.w + c.w + d.w));
    }
    {
        float4 a = *(const float4*)(e0 + 4), b = *(const float4*)(e1 + 4);
        float4 c = *(const float4*)(d0 + 4), d = *(const float4*)(d1 + 4);
        o.z = pack_h2(fast_tanh(a.x + b.x + c.x + d.x), fast_tanh(a.y + b.y + c.y + d.y));
        o.w = pack_h2(fast_tanh(a.z + b.z + c.z + d.z), fast_tanh(a.w + b.w + c.w + d.w));
    }
    *(uint4*)(g_hidden + (size_t)row * kInner + c8) = o;
}

// ---------------- K3: fp16 mma GEMM, BM=128 BN=128, 2 CTAs/SM -----------------
// 256 threads, 8 warps (2x4), warp tile 64x32. A+B cp.async double-buffered.
constexpr int SMA = 0;             // A: 2 x 128 x 128B = 32KB
constexpr int SMB = 32768;         // B: 2 x 128 x 128B = 32KB
constexpr int SMEM_TOTAL = 65536;  // 64KB -> 2 CTAs/SM

__global__ __launch_bounds__(256, 2)
void gemm_kernel(const float* __restrict__ b2, float* __restrict__ out)
{
    extern __shared__ char smem[];
    const uint32_t sb = smem_u32(smem);
    const int tid = threadIdx.x;
    const int lane = tid & 31, wid = tid >> 5;
    const int wm = wid >> 2, wn = wid & 3;
    const int bmp = blockIdx.x;

    // producer mapping: 2 threads/row, 4 x 16B chunks each (A and B identical shape)
    const int prow = tid >> 1, ppart = tid & 1, pr7 = prow & 7;
    const __half* ap = g_hidden + (size_t)(bmp * 128 + prow) * kInner;
    const __half* bp = g_w2h + (size_t)prow * kInner;
    const uint32_t a_sts = sb + SMA + prow * 128;
    const uint32_t b_sts = sb + SMB + prow * 128;

#define PRODUCE(s, buf) do { \
    const int kt_ = ((s) & 7) * 64, bn_ = (s) >> 3; \
    const __half* as_ = ap + kt_; \
    const __half* bs_ = bp + (size_t)bn_ * 128 * kInner + kt_; \
    _Pragma("unroll") \
    for (int j = 0; j < 4; j++) { \
        const int c_ = ppart * 4 + j; \
        cpasync16(a_sts + (buf) * 16384 + ((c_ ^ pr7) * 16), as_ + c_ * 8); \
        cpasync16(b_sts + (buf) * 16384 + ((c_ ^ pr7) * 16), bs_ + c_ * 8); \
    } } while (0)

    PRODUCE(0, 0);
    CP_COMMIT();
    CP_WAIT0();
    __syncthreads();

    float acc[4][4][4];
#pragma unroll
    for (int mt = 0; mt < 4; mt++)
#pragma unroll
        for (int nt = 0; nt < 4; nt++)
#pragma unroll
            for (int i = 0; i < 4; i++) acc[mt][nt][i] = 0.f;

    const int rbase = bmp * 128 + wm * 64;
    const int g2 = lane >> 2, l2 = lane & 3;

    // ---- mainloop: 128 stages = 16 bn tiles x 8 k-stages ----
#pragma unroll 1
    for (int s = 0; s < 128; s++) {
        const int buf = s & 1;
        if (s < 127) PRODUCE(s + 1, buf ^ 1);
        CP_COMMIT();
        const uint32_t Ab = sb + SMA + buf * 16384;
        const uint32_t Bb = sb + SMB + buf * 16384;
#pragma unroll
        for (int kc = 0; kc < 4; kc++) {
            uint32_t afr[4][4], bfr[4][2];
#pragma unroll
            for (int mt = 0; mt < 4; mt++) {
                const int row = wm * 64 + mt * 16 + (lane & 15);
                const int ch = (kc * 2 + (lane >> 4)) ^ (lane & 7);
                LDSM_X4(afr[mt][0], afr[mt][1], afr[mt][2], afr[mt][3],
                        Ab + row * 128 + ch * 16);
            }
#pragma unroll
            for (int np = 0; np < 2; np++) {
                const int n = wn * 32 + np * 16 + (lane & 7) + ((lane >> 4) << 3);
                const int ch = (kc * 2 + ((lane >> 3) & 1)) ^ (lane & 7);
                LDSM_X4(bfr[np * 2][0], bfr[np * 2][1], bfr[np * 2 + 1][0], bfr[np * 2 + 1][1],
                        Bb + n * 128 + ch * 16);
            }
#pragma unroll
            for (int mt = 0; mt < 4; mt++)
#pragma unroll
                for (int nt = 0; nt < 4; nt++)
                    mma16816(acc[mt][nt], afr[mt], bfr[nt]);
        }
        if ((s & 7) == 7) {
            const int bn = s >> 3;
            const int cbase = bn * 128 + wn * 32;
#pragma unroll
            for (int nt = 0; nt < 4; nt++) {
                const int c0 = cbase + nt * 8 + l2 * 2;
                const float2 bb = *(const float2*)(b2 + c0);
#pragma unroll
                for (int mt = 0; mt < 4; mt++) {
                    const int r0 = rbase + mt * 16 + g2;
                    float2 v0 = make_float2(acc[mt][nt][0] + bb.x, acc[mt][nt][1] + bb.y);
                    float2 v1 = make_float2(acc[mt][nt][2] + bb.x, acc[mt][nt][3] + bb.y);
                    stcs_f2(out + (size_t)r0 * kVocab + c0, v0);
                    stcs_f2(out + (size_t)(r0 + 8) * kVocab + c0, v1);
#pragma unroll
                    for (int i = 0; i < 4; i++) acc[mt][nt][i] = 0.f;
                }
            }
        }
        CP_WAIT0();
        __syncthreads();
    }
}

// ---------------------------------------------------------------------------
extern "C" void kernel_launch(void* const* d_in, const int* in_sizes, int n_in,
                              void* d_out, int out_size)
{
    const float* enc = (const float*)d_in[0];
    const float* dec = (const float*)d_in[1];
    const float* W1  = (const float*)d_in[2];
    const float* b1  = (const float*)d_in[3];
    const float* W2  = (const float*)d_in[4];
    const float* b2  = (const float*)d_in[5];
    float* out = (float*)d_out;

    cudaFuncSetAttribute(gemm_kernel,
                         cudaFuncAttributeMaxDynamicSharedMemorySize, SMEM_TOTAL);

    prep_kernel<<<1024 + 640, 256>>>(enc, dec, W1, b1, W2);
    hidden_kernel<<<(kMRows * (kInner / 8)) / 256, 256>>>();
    gemm_kernel<<<kMRows / 128, 256, SMEM_TOTAL>>>(b2, out);
}

// round 15
// speedup vs baseline: 1.0252x; 1.0252x over previous
#include <cuda_runtime.h>
#include <cuda_fp16.h>
#include <cstdint>

constexpr int kD = 512, kInner = 512, kVocab = 2048;
constexpr int kEncRows = 1024, kDecRows = 256, kMRows = 65536;

__device__ float g_eproj2[2][kEncRows * kInner];   // K-split halves of enc @ We (+b1 in half 0)
__device__ float g_dproj2[2][kDecRows * kInner];   // K-split halves of dec @ Wd
__device__ __half g_w2h[(size_t)kVocab * kInner];  // W2^T as fp16, [v][k]

// ---------------- helpers ----------------
__device__ __forceinline__ uint32_t smem_u32(const void* p) {
    uint32_t a;
    asm("{ .reg .u64 t; cvta.to.shared.u64 t, %1; cvt.u32.u64 %0, t; }" : "=r"(a) : "l"(p));
    return a;
}
#define CP_COMMIT()  asm volatile("cp.async.commit_group;" ::: "memory")
#define CP_WAIT(n)   asm volatile("cp.async.wait_group %0;" :: "n"(n) : "memory")
#define BAR_SYNC(id, cnt)   asm volatile("bar.sync %0, %1;"   :: "r"(id), "r"(cnt) : "memory")
#define BAR_ARRIVE(id, cnt) asm volatile("bar.arrive %0, %1;" :: "r"(id), "r"(cnt) : "memory")
__device__ __forceinline__ void cpasync16(uint32_t dst, const void* src) {
    asm volatile("cp.async.cg.shared.global [%0], [%1], 16;" :: "r"(dst), "l"(src) : "memory");
}
#define LDSM_X4(r0, r1, r2, r3, a) \
    asm volatile("ldmatrix.sync.aligned.m8n8.x4.shared.b16 {%0,%1,%2,%3}, [%4];" \
                 : "=r"(r0), "=r"(r1), "=r"(r2), "=r"(r3) : "r"(a))
__device__ __forceinline__ void mma16816(float* c, const uint32_t* a, const uint32_t* b) {
    asm volatile("mma.sync.aligned.m16n8k16.row.col.f32.f16.f16.f32 "
                 "{%0,%1,%2,%3}, {%4,%5,%6,%7}, {%8,%9}, {%0,%1,%2,%3};"
                 : "+f"(c[0]), "+f"(c[1]), "+f"(c[2]), "+f"(c[3])
                 : "r"(a[0]), "r"(a[1]), "r"(a[2]), "r"(a[3]), "r"(b[0]), "r"(b[1]));
}
__device__ __forceinline__ void sts128(uint32_t a, uint32_t x, uint32_t y, uint32_t z, uint32_t w) {
    asm volatile("st.shared.v4.b32 [%0], {%1,%2,%3,%4};" :: "r"(a), "r"(x), "r"(y), "r"(z), "r"(w) : "memory");
}
__device__ __forceinline__ void stcs_f2(float* p, float2 v) {
    asm volatile("st.global.cs.v2.f32 [%0], {%1,%2};" :: "l"(p), "f"(v.x), "f"(v.y) : "memory");
}
// proven tanh (same formulation that measured rel_err 2.854e-4)
__device__ __forceinline__ float fast_tanh(float x) {
    float e = __expf(2.0f * x);
    return 1.0f - __fdividef(2.0f, e + 1.0f);
}
__device__ __forceinline__ uint32_t pack_h2(float lo, float hi) {
    uint32_t r;
    asm("cvt.rn.f16x2.f32 %0, %1, %2;" : "=r"(r) : "f"(hi), "f"(lo));
    return r;
}

// ---------------- K1: prep = proj (K-split x2, 640 blocks) + w2h (1024 blocks) --
__global__ void prep_kernel(const float* __restrict__ enc, const float* __restrict__ dec,
                            const float* __restrict__ W1, const float* __restrict__ b1,
                            const float* __restrict__ W2)
{
    const int bid = blockIdx.x;
    const int tid = threadIdx.x;
    if (bid < 1024) {
        __shared__ float tile[32][33];
        const int tx = tid & 31, ty = tid >> 5;
        const int v0 = (bid & 63) * 32, k0 = (bid >> 6) * 32;
#pragma unroll
        for (int i = 0; i < 4; i++)
            tile[ty + i * 8][tx] = W2[(size_t)(k0 + ty + i * 8) * kVocab + v0 + tx];
        __syncthreads();
#pragma unroll
        for (int i = 0; i < 4; i++)
            g_w2h[(size_t)(v0 + ty + i * 8) * kInner + k0 + tx] = __float2half_rn(tile[tx][ty + i * 8]);
        return;
    }
    __shared__ float As[16][34];
    __shared__ float Ws[16][64];
    const int bid2 = bid - 1024;
    const int bm = bid2 >> 4;
    const int bn = (bid2 & 15) >> 1;
    const int half = bid2 & 1;
    const int row0 = bm * 32;
    const bool is_enc = row0 < kEncRows;
    const float* in = (is_enc ? (enc + row0 * kD) : (dec + (row0 - kEncRows) * kD)) + half * 256;
    const float* W  = (is_enc ? W1 : (W1 + kD * kInner)) + (size_t)half * 256 * kInner;
    const int tx = tid & 15, ty = tid >> 4;

    float acc[2][4];
#pragma unroll
    for (int i = 0; i < 2; i++)
#pragma unroll
        for (int j = 0; j < 4; j++) acc[i][j] = 0.f;

    for (int kt = 0; kt < 16; kt++) {
        float2 av = *(const float2*)(in + (tid >> 3) * kD + kt * 16 + (tid & 7) * 2);
        float4 wv = *(const float4*)(W + (kt * 16 + (tid >> 4)) * kInner + bn * 64 + (tid & 15) * 4);
        As[(tid & 7) * 2 + 0][tid >> 3] = av.x;
        As[(tid & 7) * 2 + 1][tid >> 3] = av.y;
        *(float4*)&Ws[tid >> 4][(tid & 15) * 4] = wv;
        __syncthreads();
#pragma unroll
        for (int k = 0; k < 16; k++) {
            float ar[2], br[4];
#pragma unroll
            for (int i = 0; i < 2; i++) ar[i] = As[k][ty * 2 + i];
#pragma unroll
            for (int j = 0; j < 4; j++) br[j] = Ws[k][tx * 4 + j];
#pragma unroll
            for (int i = 0; i < 2; i++)
#pragma unroll
                for (int j = 0; j < 4; j++) acc[i][j] += ar[i] * br[j];
        }
        __syncthreads();
    }
    float* outp = is_enc ? g_eproj2[half] : g_dproj2[half];
    const int obase = is_enc ? row0 : (row0 - kEncRows);
#pragma unroll
    for (int i = 0; i < 2; i++)
#pragma unroll
        for (int j = 0; j < 4; j++) {
            const int n = bn * 64 + tx * 4 + j;
            float v = acc[i][j];
            if (is_enc && half == 0) v += b1[n];
            outp[(obase + ty * 2 + i) * kInner + n] = v;
        }
}

// ---------------- K3: fused tanh + fp16 mma GEMM, warp-specialized ------------
// BM=128 (full K=512 A persistent, 128KB), BN=128, 4-stage B ring (4x16KB).
// 512 threads: warps 0-7 consumers (2x4, warp tile 64x32), warps 8-15 producers.
// Named barriers: full[i] -> id 1+i, empty[i] -> id 5+i (i = stage % 4).
constexpr int SMA = 0;              // A: 8 x 128 x 128B = 128KB
constexpr int SMB = 131072;         // B ring: 4 x 128 x 128B = 64KB
constexpr int SMEM_TOTAL = 196608;  // 192KB
constexpr int NSTAGES = 128;        // 16 bn tiles x 8 k-stages

__global__ __launch_bounds__(512, 1)
void fused_joint_kernel(const float* __restrict__ b2, float* __restrict__ out)
{
    extern __shared__ char smem[];
    const uint32_t sb = smem_u32(smem);
    const int tid = threadIdx.x;
    const int lane = tid & 31, wid = tid >> 5;
    const int bmp = blockIdx.x;

    // ---- A prologue: all 512 threads produce tanh A (R6-proven mapping) ----
    {
        const int arow = tid >> 2, apart = tid & 3;
        const int gm = bmp * 128 + arow;
        const size_t eoff = (size_t)(gm >> 6) * kInner + apart * 16;
        const size_t doff = (size_t)(((gm >> 14) << 6) | (gm & 63)) * kInner + apart * 16;
        const float* e0p = g_eproj2[0] + eoff;
        const float* e1p = g_eproj2[1] + eoff;
        const float* d0p = g_dproj2[0] + doff;
        const float* d1p = g_dproj2[1] + doff;
        const uint32_t a_sts = sb + SMA + arow * 128;
        const int ar7 = arow & 7;
#pragma unroll 1
        for (int kt = 0; kt < 8; kt++) {
            const uint32_t ab_ = a_sts + kt * 16384;
#pragma unroll
            for (int j = 0; j < 2; j++) {
                const int k = kt * 64 + j * 8;
                float4 ea0 = *(const float4*)(e0p + k);
                float4 eb0 = *(const float4*)(e1p + k);
                float4 da0 = *(const float4*)(d0p + k);
                float4 db0 = *(const float4*)(d1p + k);
                float4 ea1 = *(const float4*)(e0p + k + 4);
                float4 eb1 = *(const float4*)(e1p + k + 4);
                float4 da1 = *(const float4*)(d0p + k + 4);
                float4 db1 = *(const float4*)(d1p + k + 4);
                uint32_t h0 = pack_h2(fast_tanh(ea0.x + eb0.x + da0.x + db0.x),
                                      fast_tanh(ea0.y + eb0.y + da0.y + db0.y));
                uint32_t h1 = pack_h2(fast_tanh(ea0.z + eb0.z + da0.z + db0.z),
                                      fast_tanh(ea0.w + eb0.w + da0.w + db0.w));
                uint32_t h2 = pack_h2(fast_tanh(ea1.x + eb1.x + da1.x + db1.x),
                                      fast_tanh(ea1.y + eb1.y + da1.y + db1.y));
                uint32_t h3 = pack_h2(fast_tanh(ea1.z + eb1.z + da1.z + db1.z),
                                      fast_tanh(ea1.w + eb1.w + da1.w + db1.w));
                const int c_ = apart * 2 + j;
                sts128(ab_ + ((c_ ^ ar7) * 16), h0, h1, h2, h3);
            }
        }
    }
    __syncthreads();

    if (wid >= 8) {
        // ======================= PRODUCER (warps 8-15) =======================
        // R13-proven mapping: 2 threads/row; ppart selects 32-half (4-chunk) half.
        const int ptid = tid - 256;                 // 0..255
        const int prow = ptid >> 1, ppart = ptid & 1, pr7 = prow & 7;
        const __half* wp = g_w2h + (size_t)prow * kInner + ppart * 32;
        const uint32_t b_sts = sb + SMB + prow * 128;
#pragma unroll 1
        for (int s = 0; s < NSTAGES; s++) {
            const int ring = s & 3;
            if (s >= 4) BAR_SYNC(5 + ring, 512);    // wait consumer freed buf
            const __half* src = wp + (size_t)(s >> 3) * 128 * kInner + (s & 7) * 64;
            const uint32_t bb = b_sts + ring * 16384;
#pragma unroll
            for (int j = 0; j < 4; j++) {
                const int c_ = ppart * 4 + j;
                cpasync16(bb + ((c_ ^ pr7) * 16), src + j * 8);
            }
            CP_COMMIT();
            if (s >= 3) {
                CP_WAIT(3);
                BAR_ARRIVE(1 + ((s - 3) & 3), 512);
            }
        }
        CP_WAIT(2); BAR_ARRIVE(1 + ((NSTAGES - 3) & 3), 512);
        CP_WAIT(1); BAR_ARRIVE(1 + ((NSTAGES - 2) & 3), 512);
        CP_WAIT(0); BAR_ARRIVE(1 + ((NSTAGES - 1) & 3), 512);
    } else {
        // ======================= CONSUMER (warps 0-7) ========================
        const int wm = wid >> 2, wn = wid & 3;
        float acc[4][4][4];
#pragma unroll
        for (int mt = 0; mt < 4; mt++)
#pragma unroll
            for (int nt = 0; nt < 4; nt++)
#pragma unroll
                for (int i = 0; i < 4; i++) acc[mt][nt][i] = 0.f;

        const int rbase = bmp * 128 + wm * 64;
        const int g2 = lane >> 2, l2 = lane & 3;

#pragma unroll 1
        for (int s = 0; s < NSTAGES; s++) {
            const int ring = s & 3;
            BAR_SYNC(1 + ring, 512);                // wait buf full
            const uint32_t Ab = sb + SMA + (s & 7) * 16384;
            const uint32_t Bb = sb + SMB + ring * 16384;
#pragma unroll
            for (int kc = 0; kc < 4; kc++) {
                uint32_t afr[4][4], bfr[4][2];
#pragma unroll
                for (int mt = 0; mt < 4; mt++) {
                    const int row = wm * 64 + mt * 16 + (lane & 15);
                    const int ch = (kc * 2 + (lane >> 4)) ^ (lane & 7);
                    LDSM_X4(afr[mt][0], afr[mt][1], afr[mt][2], afr[mt][3],
                            Ab + row * 128 + ch * 16);
                }
#pragma unroll
                for (int np = 0; np < 2; np++) {
                    const int n = wn * 32 + np * 16 + (lane & 7) + ((lane >> 4) << 3);
                    const int ch = (kc * 2 + ((lane >> 3) & 1)) ^ (lane & 7);
                    LDSM_X4(bfr[np * 2][0], bfr[np * 2][1], bfr[np * 2 + 1][0], bfr[np * 2 + 1][1],
                            Bb + n * 128 + ch * 16);
                }
#pragma unroll
                for (int mt = 0; mt < 4; mt++)
#pragma unroll
                    for (int nt = 0; nt < 4; nt++)
                        mma16816(acc[mt][nt], afr[mt], bfr[nt]);
            }
            BAR_ARRIVE(5 + ring, 512);              // free buf
            if ((s & 7) == 7) {
                const int bn = s >> 3;
                const int cbase = bn * 128 + wn * 32;
#pragma unroll
                for (int nt = 0; nt < 4; nt++) {
                    const int c0 = cbase + nt * 8 + l2 * 2;
                    const float2 bb = *(const float2*)(b2 + c0);
#pragma unroll
                    for (int mt = 0; mt < 4; mt++) {
                        const int r0 = rbase + mt * 16 + g2;
                        float2 v0 = make_float2(acc[mt][nt][0] + bb.x, acc[mt][nt][1] + bb.y);
                        float2 v1 = make_float2(acc[mt][nt][2] + bb.x, acc[mt][nt][3] + bb.y);
                        stcs_f2(out + (size_t)r0 * kVocab + c0, v0);
                        stcs_f2(out + (size_t)(r0 + 8) * kVocab + c0, v1);
#pragma unroll
                        for (int i = 0; i < 4; i++) acc[mt][nt][i] = 0.f;
                    }
                }
            }
        }
    }
}

// ---------------------------------------------------------------------------
extern "C" void kernel_launch(void* const* d_in, const int* in_sizes, int n_in,
                              void* d_out, int out_size)
{
    const float* enc = (const float*)d_in[0];
    const float* dec = (const float*)d_in[1];
    const float* W1  = (const float*)d_in[2];
    const float* b1  = (const float*)d_in[3];
    const float* W2  = (const float*)d_in[4];
    const float* b2  = (const float*)d_in[5];
    float* out = (float*)d_out;

    cudaFuncSetAttribute(fused_joint_kernel,
                         cudaFuncAttributeMaxDynamicSharedMemorySize, SMEM_TOTAL);

    prep_kernel<<<1024 + 640, 256>>>(enc, dec, W1, b1, W2);
    fused_joint_kernel<<<kMRows / 128, 512, SMEM_TOTAL>>>(b2, out);
}

// round 17
// speedup vs baseline: 1.1601x; 1.1316x over previous
#include <cuda_runtime.h>
#include <cuda_fp16.h>
#include <cstdint>

constexpr int kD = 512, kInner = 512, kVocab = 2048;
constexpr int kEncRows = 1024, kDecRows = 256, kMRows = 65536;

__device__ float g_eproj2[2][kEncRows * kInner];   // K-split halves of enc @ We (+b1 in half 0)
__device__ float g_dproj2[2][kDecRows * kInner];   // K-split halves of dec @ Wd
__device__ __half g_w2h[(size_t)kVocab * kInner];  // W2^T as fp16, [v][k]

// ---------------- helpers ----------------
__device__ __forceinline__ uint32_t smem_u32(const void* p) {
    uint32_t a;
    asm("{ .reg .u64 t; cvta.to.shared.u64 t, %1; cvt.u32.u64 %0, t; }" : "=r"(a) : "l"(p));
    return a;
}
#define CP_COMMIT() asm volatile("cp.async.commit_group;" ::: "memory")
#define CP_WAIT0()  asm volatile("cp.async.wait_group 0;" ::: "memory")
__device__ __forceinline__ void cpasync16(uint32_t dst, const void* src) {
    asm volatile("cp.async.cg.shared.global [%0], [%1], 16;" :: "r"(dst), "l"(src) : "memory");
}
#define LDSM_X4(r0, r1, r2, r3, a) \
    asm volatile("ldmatrix.sync.aligned.m8n8.x4.shared.b16 {%0,%1,%2,%3}, [%4];" \
                 : "=r"(r0), "=r"(r1), "=r"(r2), "=r"(r3) : "r"(a))
__device__ __forceinline__ void mma16816(float* c, const uint32_t* a, const uint32_t* b) {
    asm volatile("mma.sync.aligned.m16n8k16.row.col.f32.f16.f16.f32 "
                 "{%0,%1,%2,%3}, {%4,%5,%6,%7}, {%8,%9}, {%0,%1,%2,%3};"
                 : "+f"(c[0]), "+f"(c[1]), "+f"(c[2]), "+f"(c[3])
                 : "r"(a[0]), "r"(a[1]), "r"(a[2]), "r"(a[3]), "r"(b[0]), "r"(b[1]));
}
__device__ __forceinline__ void sts128(uint32_t a, uint32_t x, uint32_t y, uint32_t z, uint32_t w) {
    asm volatile("st.shared.v4.b32 [%0], {%1,%2,%3,%4};" :: "r"(a), "r"(x), "r"(y), "r"(z), "r"(w) : "memory");
}
__device__ __forceinline__ void stcs_f2(float* p, float2 v) {
    asm volatile("st.global.cs.v2.f32 [%0], {%1,%2};" :: "l"(p), "f"(v.x), "f"(v.y) : "memory");
}
// proven tanh (same formulation that measured rel_err 2.854e-4)
__device__ __forceinline__ float fast_tanh(float x) {
    float e = __expf(2.0f * x);
    return 1.0f - __fdividef(2.0f, e + 1.0f);
}
__device__ __forceinline__ uint32_t pack_h2(float lo, float hi) {
    uint32_t r;
    asm("cvt.rn.f16x2.f32 %0, %1, %2;" : "=r"(r) : "f"(hi), "f"(lo));
    return r;
}

// ---------------- K1: prep = proj (K-split x2, 640 blocks) + w2h (1024 blocks) --
__global__ void prep_kernel(const float* __restrict__ enc, const float* __restrict__ dec,
                            const float* __restrict__ W1, const float* __restrict__ b1,
                            const float* __restrict__ W2)
{
    const int bid = blockIdx.x;
    const int tid = threadIdx.x;
    if (bid < 1024) {
        __shared__ float tile[32][33];
        const int tx = tid & 31, ty = tid >> 5;
        const int v0 = (bid & 63) * 32, k0 = (bid >> 6) * 32;
#pragma unroll
        for (int i = 0; i < 4; i++)
            tile[ty + i * 8][tx] = W2[(size_t)(k0 + ty + i * 8) * kVocab + v0 + tx];
        __syncthreads();
#pragma unroll
        for (int i = 0; i < 4; i++)
            g_w2h[(size_t)(v0 + ty + i * 8) * kInner + k0 + tx] = __float2half_rn(tile[tx][ty + i * 8]);
        return;
    }
    __shared__ float As[16][34];
    __shared__ float Ws[16][64];
    const int bid2 = bid - 1024;
    const int bm = bid2 >> 4;
    const int bn = (bid2 & 15) >> 1;
    const int half = bid2 & 1;
    const int row0 = bm * 32;
    const bool is_enc = row0 < kEncRows;
    const float* in = (is_enc ? (enc + row0 * kD) : (dec + (row0 - kEncRows) * kD)) + half * 256;
    const float* W  = (is_enc ? W1 : (W1 + kD * kInner)) + (size_t)half * 256 * kInner;
    const int tx = tid & 15, ty = tid >> 4;

    float acc[2][4];
#pragma unroll
    for (int i = 0; i < 2; i++)
#pragma unroll
        for (int j = 0; j < 4; j++) acc[i][j] = 0.f;

    for (int kt = 0; kt < 16; kt++) {
        float2 av = *(const float2*)(in + (tid >> 3) * kD + kt * 16 + (tid & 7) * 2);
        float4 wv = *(const float4*)(W + (kt * 16 + (tid >> 4)) * kInner + bn * 64 + (tid & 15) * 4);
        As[(tid & 7) * 2 + 0][tid >> 3] = av.x;
        As[(tid & 7) * 2 + 1][tid >> 3] = av.y;
        *(float4*)&Ws[tid >> 4][(tid & 15) * 4] = wv;
        __syncthreads();
#pragma unroll
        for (int k = 0; k < 16; k++) {
            float ar[2], br[4];
#pragma unroll
            for (int i = 0; i < 2; i++) ar[i] = As[k][ty * 2 + i];
#pragma unroll
            for (int j = 0; j < 4; j++) br[j] = Ws[k][tx * 4 + j];
#pragma unroll
            for (int i = 0; i < 2; i++)
#pragma unroll
                for (int j = 0; j < 4; j++) acc[i][j] += ar[i] * br[j];
        }
        __syncthreads();
    }
    float* outp = is_enc ? g_eproj2[half] : g_dproj2[half];
    const int obase = is_enc ? row0 : (row0 - kEncRows);
#pragma unroll
    for (int i = 0; i < 2; i++)
#pragma unroll
        for (int j = 0; j < 4; j++) {
            const int n = bn * 64 + tx * 4 + j;
            float v = acc[i][j];
            if (is_enc && half == 0) v += b1[n];
            outp[(obase + ty * 2 + i) * kInner + n] = v;
        }
}

// ---------------- K3: fused tanh + fp16 mma GEMM, persistent A (R6 inner loop) -
// Grid (2, 512): blockIdx.y = M-tile (BM=128), blockIdx.x = bn-half (4 of 8 tiles).
// 512 threads, 16 warps (2x8), warp tile 64x32, BN=256, BK=64, 2-stage B.
constexpr int SMA = 0;              // A: 8 x 128 x 128B = 128KB
constexpr int SMB = 131072;         // B: 2 x 256 x 128B = 64KB
constexpr int SMEM_TOTAL = 196608;  // 192KB

__global__ __launch_bounds__(512, 1)
void fused_joint_kernel(const float* __restrict__ b2, float* __restrict__ out)
{
    extern __shared__ char smem[];
    const uint32_t sb = smem_u32(smem);
    const int tid = threadIdx.x;
    const int lane = tid & 31, wid = tid >> 5;
    const int wm = wid >> 3, wn = wid & 7;
    const int bmp = blockIdx.y;
    const int half = blockIdx.x;        // bn tiles [half*4, half*4+4)

    // A producer mapping: 4 threads/row, 16 k-elems each
    const int arow = tid >> 2, apart = tid & 3;
    const int gm = bmp * 128 + arow;
    const size_t eoff = (size_t)(gm >> 6) * kInner + apart * 16;
    const size_t doff = (size_t)(((gm >> 14) << 6) | (gm & 63)) * kInner + apart * 16;
    const float* e0p = g_eproj2[0] + eoff;
    const float* e1p = g_eproj2[1] + eoff;
    const float* d0p = g_dproj2[0] + doff;
    const float* d1p = g_dproj2[1] + doff;
    const uint32_t a_sts = sb + SMA + arow * 128;
    const int ar7 = arow & 7;
    // B producer mapping: 2 threads/row, 4 x 16B chunks each
    const int brow = tid >> 1;
    const __half* wp = g_w2h + (size_t)brow * kInner + (tid & 1) * 32;
    const uint32_t b_sts = sb + SMB + brow * 128;
    const int br7 = brow & 7;

#define PRODUCE_B(s, buf) do { \
    const __half* wps_ = wp + (size_t)(half * 4 + ((s) >> 3)) * 256 * kInner + ((s) & 7) * 64; \
    const uint32_t bb_ = b_sts + (buf) * 32768; \
    _Pragma("unroll") \
    for (int j = 0; j < 4; j++) { \
        const int c_ = (tid & 1) * 4 + j; \
        cpasync16(bb_ + ((c_ ^ br7) * 16), wps_ + j * 8); \
    } } while (0)

    // ---- prologue: stage-0 B load overlapped with full-A tanh production ----
    PRODUCE_B(0, 0);
    CP_COMMIT();
#pragma unroll 1
    for (int kt = 0; kt < 8; kt++) {
        const uint32_t ab_ = a_sts + kt * 16384;
#pragma unroll
        for (int j = 0; j < 2; j++) {
            const int k = kt * 64 + j * 8;
            float4 ea0 = *(const float4*)(e0p + k);
            float4 eb0 = *(const float4*)(e1p + k);
            float4 da0 = *(const float4*)(d0p + k);
            float4 db0 = *(const float4*)(d1p + k);
            float4 ea1 = *(const float4*)(e0p + k + 4);
            float4 eb1 = *(const float4*)(e1p + k + 4);
            float4 da1 = *(const float4*)(d0p + k + 4);
            float4 db1 = *(const float4*)(d1p + k + 4);
            uint32_t h0 = pack_h2(fast_tanh(ea0.x + eb0.x + da0.x + db0.x),
                                  fast_tanh(ea0.y + eb0.y + da0.y + db0.y));
            uint32_t h1 = pack_h2(fast_tanh(ea0.z + eb0.z + da0.z + db0.z),
                                  fast_tanh(ea0.w + eb0.w + da0.w + db0.w));
            uint32_t h2 = pack_h2(fast_tanh(ea1.x + eb1.x + da1.x + db1.x),
                                  fast_tanh(ea1.y + eb1.y + da1.y + db1.y));
            uint32_t h3 = pack_h2(fast_tanh(ea1.z + eb1.z + da1.z + db1.z),
                                  fast_tanh(ea1.w + eb1.w + da1.w + db1.w));
            const int c_ = apart * 2 + j;
            sts128(ab_ + ((c_ ^ ar7) * 16), h0, h1, h2, h3);
        }
    }
    CP_WAIT0();
    __syncthreads();

    float acc[4][4][4];
#pragma unroll
    for (int mt = 0; mt < 4; mt++)
#pragma unroll
        for (int nt = 0; nt < 4; nt++)
#pragma unroll
            for (int i = 0; i < 4; i++) acc[mt][nt][i] = 0.f;

    const int rbase = bmp * 128 + wm * 64;
    const int g2 = lane >> 2, l2 = lane & 3;

    // ---- mainloop: 32 stages = 4 bn tiles x 8 k-stages ----
#pragma unroll 1
    for (int s = 0; s < 32; s++) {
        const int buf = s & 1;
        if (s < 31) PRODUCE_B(s + 1, buf ^ 1);
        CP_COMMIT();
        const uint32_t Ab = sb + SMA + (s & 7) * 16384;
        const uint32_t Bb = sb + SMB + buf * 32768;
#pragma unroll
        for (int kc = 0; kc < 4; kc++) {
            uint32_t afr[4][4], bfr[4][2];
#pragma unroll
            for (int mt = 0; mt < 4; mt++) {
                const int row = wm * 64 + mt * 16 + (lane & 15);
                const int ch = (kc * 2 + (lane >> 4)) ^ (lane & 7);
                LDSM_X4(afr[mt][0], afr[mt][1], afr[mt][2], afr[mt][3],
                        Ab + row * 128 + ch * 16);
            }
#pragma unroll
            for (int np = 0; np < 2; np++) {
                const int n = wn * 32 + np * 16 + (lane & 7) + ((lane >> 4) << 3);
                const int ch = (kc * 2 + ((lane >> 3) & 1)) ^ (lane & 7);
                LDSM_X4(bfr[np * 2][0], bfr[np * 2][1], bfr[np * 2 + 1][0], bfr[np * 2 + 1][1],
                        Bb + n * 128 + ch * 16);
            }
#pragma unroll
            for (int mt = 0; mt < 4; mt++)
#pragma unroll
                for (int nt = 0; nt < 4; nt++)
                    mma16816(acc[mt][nt], afr[mt], bfr[nt]);
        }
        if ((s & 7) == 7) {
            // finished bn tile: add b2, write out, reset acc
            const int bn = half * 4 + (s >> 3);
            const int cbase = bn * 256 + wn * 32;
#pragma unroll
            for (int nt = 0; nt < 4; nt++) {
                const int c0 = cbase + nt * 8 + l2 * 2;
                const float2 bb = *(const float2*)(b2 + c0);
#pragma unroll
                for (int mt = 0; mt < 4; mt++) {
                    const int r0 = rbase + mt * 16 + g2;
                    float2 v0 = make_float2(acc[mt][nt][0] + bb.x, acc[mt][nt][1] + bb.y);
                    float2 v1 = make_float2(acc[mt][nt][2] + bb.x, acc[mt][nt][3] + bb.y);
                    stcs_f2(out + (size_t)r0 * kVocab + c0, v0);
                    stcs_f2(out + (size_t)(r0 + 8) * kVocab + c0, v1);
#pragma unroll
                    for (int i = 0; i < 4; i++) acc[mt][nt][i] = 0.f;
                }
            }
        }
        CP_WAIT0();
        __syncthreads();
    }
}

// ---------------------------------------------------------------------------
extern "C" void kernel_launch(void* const* d_in, const int* in_sizes, int n_in,
                              void* d_out, int out_size)
{
    const float* enc = (const float*)d_in[0];
    const float* dec = (const float*)d_in[1];
    const float* W1  = (const float*)d_in[2];
    const float* b1  = (const float*)d_in[3];
    const float* W2  = (const float*)d_in[4];
    const float* b2  = (const float*)d_in[5];
    float* out = (float*)d_out;

    cudaFuncSetAttribute(fused_joint_kernel,
                         cudaFuncAttributeMaxDynamicSharedMemorySize, SMEM_TOTAL);

    prep_kernel<<<1024 + 640, 256>>>(enc, dec, W1, b1, W2);
    fused_joint_kernel<<<dim3(2, 512), 512, SMEM_TOTAL>>>(b2, out);
}